// round 4
// baseline (speedup 1.0000x reference)
#include <cuda_runtime.h>
#include <math.h>

#define HD   512      // hidden
#define ID   768      // input
#define BB   32       // batch
#define TT   512      // time
#define G4   2048     // 4*HD

// ---------------- f32x2 packed helpers (Blackwell FFMA2) ----------------
__device__ __forceinline__ void ffma2(unsigned long long& d,
                                      unsigned long long a,
                                      unsigned long long b) {
    asm("fma.rn.f32x2 %0, %1, %2, %0;" : "+l"(d) : "l"(a), "l"(b));
}
__device__ __forceinline__ unsigned long long pack2(float lo, float hi) {
    unsigned long long r;
    asm("mov.b64 %0, {%1, %2};" : "=l"(r) : "f"(lo), "f"(hi));
    return r;
}
__device__ __forceinline__ void unpack2(unsigned long long v, float& lo, float& hi) {
    asm("mov.b64 {%0, %1}, %2;" : "=f"(lo), "=f"(hi) : "l"(v));
}

// ---------------- scratch (static device memory; no allocs) ----------------
__device__ float    g_gx[(size_t)TT * BB * G4];   // [t][b][col]  (128 MiB)
__device__ float    g_hbuf[2][BB * HD];           // double-buffered h, [b][k]
__device__ unsigned g_bar_count;                  // monotonic arrivals
__device__ unsigned g_bar_gen;                    // published step count

// ---------------- init: reset barrier, seed h with h0[dir=0] ----------------
__global__ void init_kernel(const float* __restrict__ h0)
{
    int idx = blockIdx.x * blockDim.x + threadIdx.x;
    if (idx == 0) { g_bar_count = 0; g_bar_gen = 0; }
    if (idx < BB * HD) g_hbuf[0][idx] = h0[idx];
}

// ---------------- gx GEMM (unchanged from R3) ----------------
#define BM 128
#define BN 64
#define BK 16

__global__ __launch_bounds__(256) void gx_gemm_kernel(
    const float* __restrict__ x,     // [B][T][I]
    const float* __restrict__ w,     // [2048][768]
    const float* __restrict__ b1,
    const float* __restrict__ b2)
{
    __shared__ float As[BK][BM + 4];
    __shared__ float Bs[BK][BN + 4];

    int tid  = threadIdx.x;
    int brow = blockIdx.x;
    int bcol = blockIdx.y;
    int ty = tid >> 4;
    int tx = tid & 15;

    unsigned long long acc2[4][4];
    #pragma unroll
    for (int i = 0; i < 4; i++)
        #pragma unroll
        for (int j = 0; j < 4; j++) acc2[i][j] = 0ull;

    for (int k0 = 0; k0 < ID; k0 += BK) {
        #pragma unroll
        for (int i = 0; i < 8; i++) {
            int e  = i * 256 + tid;
            int r  = e >> 4;
            int kk = e & 15;
            int m  = brow * BM + r;
            int b  = m & 31, t = m >> 5;
            As[kk][r] = x[((size_t)b * TT + t) * ID + k0 + kk];
        }
        #pragma unroll
        for (int i = 0; i < 4; i++) {
            int e  = i * 256 + tid;
            int n  = e >> 4;
            int kk = e & 15;
            Bs[kk][n] = w[(size_t)(bcol * BN + n) * ID + k0 + kk];
        }
        __syncthreads();

        #pragma unroll
        for (int kk = 0; kk < BK; kk++) {
            ulonglong2 av0 = *(const ulonglong2*)&As[kk][ty * 8];
            ulonglong2 av1 = *(const ulonglong2*)&As[kk][ty * 8 + 4];
            unsigned long long ap[4] = {av0.x, av0.y, av1.x, av1.y};
            float4 bv = *(const float4*)&Bs[kk][tx * 4];
            unsigned long long bsp[4];
            bsp[0] = pack2(bv.x, bv.x);
            bsp[1] = pack2(bv.y, bv.y);
            bsp[2] = pack2(bv.z, bv.z);
            bsp[3] = pack2(bv.w, bv.w);
            #pragma unroll
            for (int ip = 0; ip < 4; ip++)
                #pragma unroll
                for (int j = 0; j < 4; j++)
                    ffma2(acc2[ip][j], ap[ip], bsp[j]);
        }
        __syncthreads();
    }

    int ncol = bcol * BN + tx * 4;
    float bias[4];
    #pragma unroll
    for (int j = 0; j < 4; j++) bias[j] = b1[ncol + j] + b2[ncol + j];

    #pragma unroll
    for (int ip = 0; ip < 4; ip++) {
        float lo[4], hi[4];
        #pragma unroll
        for (int j = 0; j < 4; j++) unpack2(acc2[ip][j], lo[j], hi[j]);
        int m0 = brow * BM + ty * 8 + 2 * ip;
        float4 v0 = {lo[0] + bias[0], lo[1] + bias[1], lo[2] + bias[2], lo[3] + bias[3]};
        float4 v1 = {hi[0] + bias[0], hi[1] + bias[1], hi[2] + bias[2], hi[3] + bias[3]};
        *(float4*)&g_gx[(size_t)m0 * G4 + ncol] = v0;
        *(float4*)&g_gx[(size_t)(m0 + 1) * G4 + ncol] = v1;
    }
}

// ---------------- backward direction: ONE cell step (unchanged) ----------------
__global__ __launch_bounds__(256) void lstm_bwd_step_kernel(
    const float* __restrict__ x,
    const float* __restrict__ h0,
    const float* __restrict__ c0,
    const float* __restrict__ w_ih,
    const float* __restrict__ w_hh,
    const float* __restrict__ b_ih,
    const float* __restrict__ b_hh,
    float* __restrict__ out)
{
    int tid = threadIdx.x;
    int b = tid & 31;
    int j = blockIdx.x * 8 + (tid >> 5);

    float acc[4] = {0.f, 0.f, 0.f, 0.f};
    const float* xrow = x + ((size_t)b * TT + (TT - 1)) * ID;
    #pragma unroll 4
    for (int k = 0; k < ID; k++) {
        float xv = xrow[k];
        #pragma unroll
        for (int g = 0; g < 4; g++)
            acc[g] += xv * w_ih[(size_t)(g * HD + j) * ID + k];
    }
    const float* hrow = h0 + BB * HD + (size_t)b * HD;
    #pragma unroll 4
    for (int k = 0; k < HD; k++) {
        float hv = hrow[k];
        #pragma unroll
        for (int g = 0; g < 4; g++)
            acc[g] += hv * w_hh[(size_t)(g * HD + j) * HD + k];
    }
    #pragma unroll
    for (int g = 0; g < 4; g++) acc[g] += b_ih[g * HD + j] + b_hh[g * HD + j];

    float ig = 1.f / (1.f + __expf(-acc[0]));
    float fg = 1.f / (1.f + __expf(-acc[1]));
    float gg = tanhf(acc[2]);
    float og = 1.f / (1.f + __expf(-acc[3]));
    float c  = fg * c0[BB * HD + (size_t)b * HD + j] + ig * gg;
    float h  = og * tanhf(c);
    out[b * 1024 + 512 + j] = fmaxf(h, 0.f);
}

// ---------------- forward recurrence ----------------
// 512 threads, 16 warps. warp = (e = warp>>1 : k-eighth, rg = warp&1 : row half).
// Per step per warp: poll global gen -> stage OWN h slice -> pair barrier (id 1+e)
// -> dots -> partials STS -> bar 9 (producers arrive, update warps sync)
// -> warps 0-3: update + h STG + gx pipeline + bar 10 + tid0 publishes gen.
#define SMEM_FLOATS (16*512 + 32*516 + 8*16*32 + 2*512)
#define SMEM_BYTES  (SMEM_FLOATS * 4)

// barrier helpers
__device__ __forceinline__ unsigned ld_relaxed_gpu(const unsigned* p) {
    unsigned v;
    asm volatile("ld.relaxed.gpu.u32 %0, [%1];" : "=r"(v) : "l"(p));
    return v;
}
__device__ __forceinline__ void fence_acqrel_gpu() {
    asm volatile("fence.acq_rel.gpu;" ::: "memory");
}
__device__ __forceinline__ unsigned atom_add_relaxed_gpu(unsigned* p, unsigned v) {
    unsigned old;
    asm volatile("atom.add.relaxed.gpu.u32 %0, [%1], %2;" : "=r"(old) : "l"(p), "r"(v));
    return old;
}
__device__ __forceinline__ void st_relaxed_gpu(unsigned* p, unsigned v) {
    asm volatile("st.relaxed.gpu.u32 [%0], %1;" :: "l"(p), "r"(v));
}
__device__ __forceinline__ void poll_gen(unsigned target) {
    if (ld_relaxed_gpu(&g_bar_gen) < target) {
        while (ld_relaxed_gpu(&g_bar_gen) < target) { }
    }
    fence_acqrel_gpu();
}

// stage this warp's h slice: batches [rg*16, rg*16+16), cols [e*64, e*64+64)
__device__ __forceinline__ void stage_h(float* h_s, const float* hsrc,
                                        int e, int rg, int lane) {
    int b    = rg * 16 + (lane >> 1);
    int half = (lane & 1) * 8;           // 8 float4 = 32 floats
    const float* src = hsrc + b * HD + e * 64 + half * 4;
    float*       dst = h_s  + b * 516 + e * 64 + half * 4;
    #pragma unroll
    for (int i = 0; i < 8; i++) {
        float4 v = __ldcg((const float4*)(src + i * 4));
        *(float4*)(dst + i * 4) = v;
    }
}

// dots: 8 rows x 64 k, FFMA2 over k pairs; write 8 partials
__device__ __forceinline__ void do_dots(const float* hp0, const float* wb0,
                                        float* part, int e, int rg, int lane) {
    unsigned long long acc[8];
    #pragma unroll
    for (int r = 0; r < 8; r++) acc[r] = 0ull;

    #pragma unroll
    for (int it = 0; it < 16; it++) {
        int k = it * 4;
        ulonglong2 h2 = *(const ulonglong2*)(hp0 + k);
        #pragma unroll
        for (int r = 0; r < 8; r++) {
            ulonglong2 w2 = *(const ulonglong2*)(wb0 + r * HD + k);
            ffma2(acc[r], w2.x, h2.x);
            ffma2(acc[r], w2.y, h2.y);
        }
    }
    #pragma unroll
    for (int r = 0; r < 8; r++) {
        float lo, hi;
        unpack2(acc[r], lo, hi);
        part[(e * 16 + rg * 8 + r) * 32 + lane] = lo + hi;
    }
}

__global__ __launch_bounds__(512) void lstm_fwd_kernel(
    const float* __restrict__ c0,
    const float* __restrict__ w_hh,   // [2048][512]
    float* __restrict__ out)
{
    extern __shared__ float sm[];
    float* w_s  = sm;                        // [16][512]
    float* h_s  = sm + 16 * 512;             // [32][516]
    float* part = h_s + 32 * 516;            // [8][16][32]
    float* gxs  = part + 8 * 16 * 32;        // [2][4][32][4]  double-buffered

    int tid  = threadIdx.x;
    int bx   = blockIdx.x;       // 0..127
    int lane = tid & 31;
    int warp = tid >> 5;         // 0..15
    int e    = warp >> 1;        // 0..7
    int rg   = warp & 1;

    // load w_hh slice: local row r -> global row (r>>2)*512 + bx*4 + (r&3)
    for (int i = tid; i < 16 * 128; i += 512) {
        int r  = i >> 7;
        int kq = i & 127;
        int col = (r >> 2) * HD + bx * 4 + (r & 3);
        *(float4*)&w_s[r * HD + kq * 4] =
            *(const float4*)&w_hh[(size_t)col * HD + kq * 4];
    }

    const float* hp0 = h_s + lane * 516 + e * 64;
    const float* wb0 = w_s + (rg * 8) * HD + e * 64;

    if (warp >= 4) {
        // -------- producer warps --------
        __syncthreads();   // wait for w_s (and gxs[0])
        for (int step = 0; step < TT; step++) {
            poll_gen((unsigned)step);
            const float* hsrc = g_hbuf[step & 1];
            stage_h(h_s, hsrc, e, rg, lane);
            asm volatile("bar.sync %0, 64;" :: "r"(1 + e));
            do_dots(hp0, wb0, part, e, rg, lane);
            asm volatile("bar.arrive 9, 512;");
        }
        return;
    }

    // -------- update warps (0..3) --------
    int u = warp;                 // unit 0..3   (gate mapping uses same id)
    int g = warp;                 // gate role for gx staging
    int b = lane;
    int j = bx * 4 + u;
    float c  = c0[(size_t)b * HD + j];
    float hv = 0.f;

    // gx pipeline: gxs[0] = gx[0]; regs = gx[1]
    const float* gx_base = g_gx + (size_t)g * HD + bx * 4;
    float4 gnext;
    {
        float4 g0 = __ldcg((const float4*)(gx_base + (size_t)(0 * BB + b) * G4));
        *(float4*)&gxs[((0 * 4 + g) * 32 + b) * 4] = g0;
        gnext = __ldcg((const float4*)(gx_base + (size_t)(1 * BB + b) * G4));
    }
    __syncthreads();   // w_s + gxs[0] visible to everyone

    for (int step = 0; step < TT; step++) {
        poll_gen((unsigned)step);
        const float* hsrc = g_hbuf[step & 1];
        stage_h(h_s, hsrc, e, rg, lane);
        asm volatile("bar.sync %0, 64;" :: "r"(1 + e));
        do_dots(hp0, wb0, part, e, rg, lane);
        asm volatile("bar.sync 9, 512;");

        // ---- elementwise update: thread (u, b) ----
        int cur = step & 1;
        float gate[4];
        #pragma unroll
        for (int gg2 = 0; gg2 < 4; gg2++) {
            int r = gg2 * 4 + u;
            float s = gxs[((cur * 4 + gg2) * 32 + b) * 4 + u];
            #pragma unroll
            for (int ee = 0; ee < 8; ee++)
                s += part[(ee * 16 + r) * 32 + b];
            gate[gg2] = s;
        }
        float ig = 1.f / (1.f + __expf(-gate[0]));
        float fg = 1.f / (1.f + __expf(-gate[1]));
        float gg = tanhf(gate[2]);
        float og = 1.f / (1.f + __expf(-gate[3]));
        c  = fg * c + ig * gg;
        hv = og * tanhf(c);
        g_hbuf[1 - cur][(size_t)b * HD + j] = hv;

        // gx pipeline: publish gx[step+1] to SMEM, prefetch gx[step+2]
        *(float4*)&gxs[(((1 - cur) * 4 + g) * 32 + b) * 4] = gnext;
        int nxt2 = step + 2 < TT ? step + 2 : TT - 1;
        gnext = __ldcg((const float4*)(gx_base + (size_t)(nxt2 * BB + b) * G4));

        asm volatile("bar.sync 10, 128;");
        if (tid == 0) {
            fence_acqrel_gpu();
            unsigned prev = atom_add_relaxed_gpu(&g_bar_count, 1u);
            if (prev == (unsigned)(step + 1) * 128u - 1u) {
                fence_acqrel_gpu();
                st_relaxed_gpu(&g_bar_gen, (unsigned)(step + 1));
            }
        }
    }

    out[b * 1024 + j] = fmaxf(hv, 0.f);
}

// ---------------- launch ----------------
extern "C" void kernel_launch(void* const* d_in, const int* in_sizes, int n_in,
                              void* d_out, int out_size)
{
    const float* x      = (const float*)d_in[0];
    const float* h0     = (const float*)d_in[1];
    const float* c0     = (const float*)d_in[2];
    const float* w_ih_f = (const float*)d_in[3];
    const float* w_hh_f = (const float*)d_in[4];
    const float* b_ih_f = (const float*)d_in[5];
    const float* b_hh_f = (const float*)d_in[6];
    const float* w_ih_b = (const float*)d_in[7];
    const float* w_hh_b = (const float*)d_in[8];
    const float* b_ih_b = (const float*)d_in[9];
    const float* b_hh_b = (const float*)d_in[10];
    float* out = (float*)d_out;

    cudaFuncSetAttribute(lstm_fwd_kernel,
                         cudaFuncAttributeMaxDynamicSharedMemorySize, SMEM_BYTES);

    init_kernel<<<64, 256>>>(h0);

    dim3 gg(128, 32);
    gx_gemm_kernel<<<gg, 256>>>(x, w_ih_f, b_ih_f, b_hh_f);

    lstm_bwd_step_kernel<<<64, 256>>>(x, h0, c0, w_ih_b, w_hh_b, b_ih_b, b_hh_b, out);

    lstm_fwd_kernel<<<128, 512, SMEM_BYTES>>>(c0, w_hh_f, out);
}

// round 5
// speedup vs baseline: 1.2352x; 1.2352x over previous
#include <cuda_runtime.h>
#include <math.h>

#define HD   512      // hidden
#define ID   768      // input
#define BB   32       // batch
#define TT   512      // time
#define G4   2048     // 4*HD

// ---------------- f32x2 packed helpers (Blackwell FFMA2) ----------------
__device__ __forceinline__ void ffma2(unsigned long long& d,
                                      unsigned long long a,
                                      unsigned long long b) {
    asm("fma.rn.f32x2 %0, %1, %2, %0;" : "+l"(d) : "l"(a), "l"(b));
}
__device__ __forceinline__ unsigned long long pack2(float lo, float hi) {
    unsigned long long r;
    asm("mov.b64 %0, {%1, %2};" : "=l"(r) : "f"(lo), "f"(hi));
    return r;
}
__device__ __forceinline__ void unpack2(unsigned long long v, float& lo, float& hi) {
    asm("mov.b64 {%0, %1}, %2;" : "=f"(lo), "=f"(hi) : "l"(v));
}

// ---------------- scratch (static device memory; no allocs) ----------------
__device__ float    g_gx[(size_t)TT * BB * G4];   // [t][b][col]  (128 MiB)
__device__ float    g_hbuf[2][BB * HD];           // double-buffered h, [b][k]
__device__ unsigned g_bar_count;                  // monotonic arrivals

// ---------------- init: reset barrier, seed h with h0[dir=0] ----------------
__global__ void init_kernel(const float* __restrict__ h0)
{
    int idx = blockIdx.x * blockDim.x + threadIdx.x;
    if (idx == 0) g_bar_count = 0;
    if (idx < BB * HD) g_hbuf[0][idx] = h0[idx];
}

// ---------------- gx GEMM (unchanged from R3) ----------------
#define BM 128
#define BN 64
#define BK 16

__global__ __launch_bounds__(256) void gx_gemm_kernel(
    const float* __restrict__ x,     // [B][T][I]
    const float* __restrict__ w,     // [2048][768]
    const float* __restrict__ b1,
    const float* __restrict__ b2)
{
    __shared__ float As[BK][BM + 4];
    __shared__ float Bs[BK][BN + 4];

    int tid  = threadIdx.x;
    int brow = blockIdx.x;
    int bcol = blockIdx.y;
    int ty = tid >> 4;
    int tx = tid & 15;

    unsigned long long acc2[4][4];
    #pragma unroll
    for (int i = 0; i < 4; i++)
        #pragma unroll
        for (int j = 0; j < 4; j++) acc2[i][j] = 0ull;

    for (int k0 = 0; k0 < ID; k0 += BK) {
        #pragma unroll
        for (int i = 0; i < 8; i++) {
            int e  = i * 256 + tid;
            int r  = e >> 4;
            int kk = e & 15;
            int m  = brow * BM + r;
            int b  = m & 31, t = m >> 5;
            As[kk][r] = x[((size_t)b * TT + t) * ID + k0 + kk];
        }
        #pragma unroll
        for (int i = 0; i < 4; i++) {
            int e  = i * 256 + tid;
            int n  = e >> 4;
            int kk = e & 15;
            Bs[kk][n] = w[(size_t)(bcol * BN + n) * ID + k0 + kk];
        }
        __syncthreads();

        #pragma unroll
        for (int kk = 0; kk < BK; kk++) {
            ulonglong2 av0 = *(const ulonglong2*)&As[kk][ty * 8];
            ulonglong2 av1 = *(const ulonglong2*)&As[kk][ty * 8 + 4];
            unsigned long long ap[4] = {av0.x, av0.y, av1.x, av1.y};
            float4 bv = *(const float4*)&Bs[kk][tx * 4];
            unsigned long long bsp[4];
            bsp[0] = pack2(bv.x, bv.x);
            bsp[1] = pack2(bv.y, bv.y);
            bsp[2] = pack2(bv.z, bv.z);
            bsp[3] = pack2(bv.w, bv.w);
            #pragma unroll
            for (int ip = 0; ip < 4; ip++)
                #pragma unroll
                for (int j = 0; j < 4; j++)
                    ffma2(acc2[ip][j], ap[ip], bsp[j]);
        }
        __syncthreads();
    }

    int ncol = bcol * BN + tx * 4;
    float bias[4];
    #pragma unroll
    for (int j = 0; j < 4; j++) bias[j] = b1[ncol + j] + b2[ncol + j];

    #pragma unroll
    for (int ip = 0; ip < 4; ip++) {
        float lo[4], hi[4];
        #pragma unroll
        for (int j = 0; j < 4; j++) unpack2(acc2[ip][j], lo[j], hi[j]);
        int m0 = brow * BM + ty * 8 + 2 * ip;
        float4 v0 = {lo[0] + bias[0], lo[1] + bias[1], lo[2] + bias[2], lo[3] + bias[3]};
        float4 v1 = {hi[0] + bias[0], hi[1] + bias[1], hi[2] + bias[2], hi[3] + bias[3]};
        *(float4*)&g_gx[(size_t)m0 * G4 + ncol] = v0;
        *(float4*)&g_gx[(size_t)(m0 + 1) * G4 + ncol] = v1;
    }
}

// ---------------- backward direction: ONE cell step (unchanged) ----------------
__global__ __launch_bounds__(256) void lstm_bwd_step_kernel(
    const float* __restrict__ x,
    const float* __restrict__ h0,
    const float* __restrict__ c0,
    const float* __restrict__ w_ih,
    const float* __restrict__ w_hh,
    const float* __restrict__ b_ih,
    const float* __restrict__ b_hh,
    float* __restrict__ out)
{
    int tid = threadIdx.x;
    int b = tid & 31;
    int j = blockIdx.x * 8 + (tid >> 5);

    float acc[4] = {0.f, 0.f, 0.f, 0.f};
    const float* xrow = x + ((size_t)b * TT + (TT - 1)) * ID;
    #pragma unroll 4
    for (int k = 0; k < ID; k++) {
        float xv = xrow[k];
        #pragma unroll
        for (int g = 0; g < 4; g++)
            acc[g] += xv * w_ih[(size_t)(g * HD + j) * ID + k];
    }
    const float* hrow = h0 + BB * HD + (size_t)b * HD;
    #pragma unroll 4
    for (int k = 0; k < HD; k++) {
        float hv = hrow[k];
        #pragma unroll
        for (int g = 0; g < 4; g++)
            acc[g] += hv * w_hh[(size_t)(g * HD + j) * HD + k];
    }
    #pragma unroll
    for (int g = 0; g < 4; g++) acc[g] += b_ih[g * HD + j] + b_hh[g * HD + j];

    float ig = 1.f / (1.f + __expf(-acc[0]));
    float fg = 1.f / (1.f + __expf(-acc[1]));
    float gg = tanhf(acc[2]);
    float og = 1.f / (1.f + __expf(-acc[3]));
    float c  = fg * c0[BB * HD + (size_t)b * HD + j] + ig * gg;
    float h  = og * tanhf(c);
    out[b * 1024 + 512 + j] = fmaxf(h, 0.f);
}

// ---------------- forward recurrence: persistent, h direct from L2, light barrier ----------------
// 512 threads, 16 warps. warp = k-segment seg (32 k), lane = batch.
// Warp computes ALL 16 local rows over its k-window, h in registers (LDG.cg),
// w broadcast from SMEM. One STS of 16 partials per lane; one syncthreads;
// update by tid<128; bar.sync 1 among updaters; tid0: red.add + poll monotonic count.
#define SMEM_FLOATS (16*512 + 16*16*32)
#define SMEM_BYTES  (SMEM_FLOATS * 4)

__device__ __forceinline__ unsigned ld_relaxed_gpu(const unsigned* p) {
    unsigned v;
    asm volatile("ld.relaxed.gpu.u32 %0, [%1];" : "=r"(v) : "l"(p));
    return v;
}
__device__ __forceinline__ void fence_acqrel_gpu() {
    asm volatile("fence.acq_rel.gpu;" ::: "memory");
}
__device__ __forceinline__ void red_add_relaxed_gpu(unsigned* p, unsigned v) {
    asm volatile("red.relaxed.gpu.global.add.u32 [%0], %1;" :: "l"(p), "r"(v));
}

__device__ __forceinline__ float fsig(float x) {         // 1/(1+e^-x)
    return __fdividef(1.f, 1.f + __expf(-x));
}
__device__ __forceinline__ float ftanh(float x) {        // 2/(1+e^-2x)-1
    return __fdividef(2.f, 1.f + __expf(-2.f * x)) - 1.f;
}

__global__ __launch_bounds__(512) void lstm_fwd_kernel(
    const float* __restrict__ c0,
    const float* __restrict__ w_hh,   // [2048][512]
    float* __restrict__ out)
{
    extern __shared__ float sm[];
    float* w_s  = sm;                        // [16][512]   r = g*4+u
    float* part = sm + 16 * 512;             // [16 seg][16 r][32 b]

    int tid  = threadIdx.x;
    int bx   = blockIdx.x;       // 0..127
    int lane = tid & 31;
    int seg  = tid >> 5;         // k-segment 0..15 -> k in [seg*32, seg*32+32)

    // load w_hh slice: local row r -> global row (r>>2)*512 + bx*4 + (r&3)
    for (int i = tid; i < 16 * 128; i += 512) {
        int r  = i >> 7;
        int kq = i & 127;
        int col = (r >> 2) * HD + bx * 4 + (r & 3);
        *(float4*)&w_s[r * HD + kq * 4] =
            *(const float4*)&w_hh[(size_t)col * HD + kq * 4];
    }

    int u = tid >> 5;            // valid for tid<128 (0..3)
    int b = lane;
    int j = bx * 4 + u;
    float c = 0.f, hv = 0.f;
    if (tid < 128) c = c0[(size_t)b * HD + j];

    const float* wseg = w_s + seg * 32;

    __syncthreads();   // w_s ready; h[0] seeded by init kernel (prior launch)

    for (int step = 0; step < TT; step++) {
        int cur = step & 1;

        // ---- h for this warp's k-window, straight from L2 into registers ----
        const float* hsrc = g_hbuf[cur] + lane * HD + seg * 32;
        float4 h4[8];
        #pragma unroll
        for (int i = 0; i < 8; i++)
            h4[i] = __ldcg((const float4*)(hsrc + i * 4));

        // ---- gx for the update phase (consumed after the sync; latency hidden) ----
        float gxv[4];
        if (tid < 128) {
            const float* gp = g_gx + (size_t)(step * BB + b) * G4 + j;
            #pragma unroll
            for (int g = 0; g < 4; g++)
                gxv[g] = __ldcg(gp + g * HD);
        }

        // ---- dots: 16 rows x 32 k, w broadcast from SMEM, h in regs ----
        unsigned long long acc[16];
        #pragma unroll
        for (int r = 0; r < 16; r++) acc[r] = 0ull;

        #pragma unroll
        for (int it = 0; it < 8; it++) {
            int k = it * 4;
            unsigned long long ha = pack2(h4[it].x, h4[it].y);
            unsigned long long hb = pack2(h4[it].z, h4[it].w);
            #pragma unroll
            for (int r = 0; r < 16; r++) {
                ulonglong2 w2 = *(const ulonglong2*)(wseg + r * HD + k);
                ffma2(acc[r], w2.x, ha);
                ffma2(acc[r], w2.y, hb);
            }
        }
        #pragma unroll
        for (int r = 0; r < 16; r++) {
            float lo, hi;
            unpack2(acc[r], lo, hi);
            part[(seg * 16 + r) * 32 + lane] = lo + hi;
        }
        __syncthreads();

        // ---- elementwise update: thread (u, b), tid<128 ----
        if (tid < 128) {
            float gate[4];
            #pragma unroll
            for (int g = 0; g < 4; g++) {
                int r = g * 4 + u;
                float s = gxv[g];
                #pragma unroll
                for (int ss = 0; ss < 16; ss++)
                    s += part[(ss * 16 + r) * 32 + b];
                gate[g] = s;
            }
            float ig = fsig(gate[0]);
            float fg = fsig(gate[1]);
            float gg = ftanh(gate[2]);
            float og = fsig(gate[3]);
            c  = fg * c + ig * gg;
            hv = og * ftanh(c);
            g_hbuf[1 - cur][(size_t)b * HD + j] = hv;

            asm volatile("bar.sync 1, 128;");   // h stores done before arrival
            if (tid == 0) {
                fence_acqrel_gpu();                       // release h stores
                red_add_relaxed_gpu(&g_bar_count, 1u);    // fire-and-forget
                unsigned target = (unsigned)(step + 1) * 128u;
                if (ld_relaxed_gpu(&g_bar_count) < target) {
                    while (ld_relaxed_gpu(&g_bar_count) < target) { }
                }
                fence_acqrel_gpu();                       // acquire others' h
            }
        }
        __syncthreads();   // release whole CTA into next step
    }

    if (tid < 128) out[b * 1024 + j] = fmaxf(hv, 0.f);
}

// ---------------- launch ----------------
extern "C" void kernel_launch(void* const* d_in, const int* in_sizes, int n_in,
                              void* d_out, int out_size)
{
    const float* x      = (const float*)d_in[0];
    const float* h0     = (const float*)d_in[1];
    const float* c0     = (const float*)d_in[2];
    const float* w_ih_f = (const float*)d_in[3];
    const float* w_hh_f = (const float*)d_in[4];
    const float* b_ih_f = (const float*)d_in[5];
    const float* b_hh_f = (const float*)d_in[6];
    const float* w_ih_b = (const float*)d_in[7];
    const float* w_hh_b = (const float*)d_in[8];
    const float* b_ih_b = (const float*)d_in[9];
    const float* b_hh_b = (const float*)d_in[10];
    float* out = (float*)d_out;

    cudaFuncSetAttribute(lstm_fwd_kernel,
                         cudaFuncAttributeMaxDynamicSharedMemorySize, SMEM_BYTES);

    init_kernel<<<64, 256>>>(h0);

    dim3 gg(128, 32);
    gx_gemm_kernel<<<gg, 256>>>(x, w_ih_f, b_ih_f, b_hh_f);

    lstm_bwd_step_kernel<<<64, 256>>>(x, h0, c0, w_ih_b, w_hh_b, b_ih_b, b_hh_b, out);

    lstm_fwd_kernel<<<128, 512, SMEM_BYTES>>>(c0, w_hh_f, out);
}

// round 6
// speedup vs baseline: 1.3368x; 1.0822x over previous
#include <cuda_runtime.h>
#include <math.h>

#define HD   512      // hidden
#define ID   768      // input
#define BB   32       // batch
#define TT   512      // time
#define G4   2048     // 4*HD

// ---------------- f32x2 packed helpers (Blackwell FFMA2) ----------------
__device__ __forceinline__ void ffma2(unsigned long long& d,
                                      unsigned long long a,
                                      unsigned long long b) {
    asm("fma.rn.f32x2 %0, %1, %2, %0;" : "+l"(d) : "l"(a), "l"(b));
}
__device__ __forceinline__ unsigned long long pack2(float lo, float hi) {
    unsigned long long r;
    asm("mov.b64 %0, {%1, %2};" : "=l"(r) : "f"(lo), "f"(hi));
    return r;
}
__device__ __forceinline__ void unpack2(unsigned long long v, float& lo, float& hi) {
    asm("mov.b64 {%0, %1}, %2;" : "=f"(lo), "=f"(hi) : "l"(v));
}

// ---------------- scratch (static device memory; no allocs) ----------------
// gx layout: [t][n][b]  (n = gate*HD + j)  -> coalesced lane=b reads in fwd
__device__ float    g_gx[(size_t)TT * G4 * BB];
// h layout: [buf][k>>2][b][k&3] -> LDG.128 per 4 k at lane-stride 16B (nL=4)
__device__ float    g_hq[2][HD / 4][BB][4];
__device__ unsigned g_bar_count;                  // monotonic arrivals

// ---------------- init: reset barrier, seed h with h0[dir=0] ----------------
__global__ void init_kernel(const float* __restrict__ h0)
{
    int idx = blockIdx.x * blockDim.x + threadIdx.x;   // over 16384
    if (idx == 0) g_bar_count = 0;
    if (idx < BB * HD) {
        int b = idx >> 9;          // /HD
        int k = idx & (HD - 1);
        g_hq[0][k >> 2][b][k & 3] = h0[idx];
    }
}

// ---------------- gx GEMM with transposed epilogue ----------------
#define BM 128
#define BN 64
#define BK 16

__global__ __launch_bounds__(256) void gx_gemm_kernel(
    const float* __restrict__ x,     // [B][T][I]
    const float* __restrict__ w,     // [2048][768]
    const float* __restrict__ b1,
    const float* __restrict__ b2)
{
    __shared__ float As[BK][BM + 4];     // 8448 B
    __shared__ float Bs[BK][BN + 4];     // 4352 B
    __shared__ float St[BM][BN + 1];     // 33280 B  (epilogue transpose tile)

    int tid  = threadIdx.x;
    int brow = blockIdx.x;   // 0..127  (M tiles; m = t*32 + b)
    int bcol = blockIdx.y;   // 0..31   (N tiles)
    int ty = tid >> 4;
    int tx = tid & 15;

    unsigned long long acc2[4][4];
    #pragma unroll
    for (int i = 0; i < 4; i++)
        #pragma unroll
        for (int j = 0; j < 4; j++) acc2[i][j] = 0ull;

    for (int k0 = 0; k0 < ID; k0 += BK) {
        #pragma unroll
        for (int i = 0; i < 8; i++) {
            int e  = i * 256 + tid;
            int r  = e >> 4;
            int kk = e & 15;
            int m  = brow * BM + r;
            int b  = m & 31, t = m >> 5;
            As[kk][r] = x[((size_t)b * TT + t) * ID + k0 + kk];
        }
        #pragma unroll
        for (int i = 0; i < 4; i++) {
            int e  = i * 256 + tid;
            int n  = e >> 4;
            int kk = e & 15;
            Bs[kk][n] = w[(size_t)(bcol * BN + n) * ID + k0 + kk];
        }
        __syncthreads();

        #pragma unroll
        for (int kk = 0; kk < BK; kk++) {
            ulonglong2 av0 = *(const ulonglong2*)&As[kk][ty * 8];
            ulonglong2 av1 = *(const ulonglong2*)&As[kk][ty * 8 + 4];
            unsigned long long ap[4] = {av0.x, av0.y, av1.x, av1.y};
            float4 bv = *(const float4*)&Bs[kk][tx * 4];
            unsigned long long bsp[4];
            bsp[0] = pack2(bv.x, bv.x);
            bsp[1] = pack2(bv.y, bv.y);
            bsp[2] = pack2(bv.z, bv.z);
            bsp[3] = pack2(bv.w, bv.w);
            #pragma unroll
            for (int ip = 0; ip < 4; ip++)
                #pragma unroll
                for (int j = 0; j < 4; j++)
                    ffma2(acc2[ip][j], ap[ip], bsp[j]);
        }
        __syncthreads();
    }

    int ncol = bcol * BN + tx * 4;
    float bias[4];
    #pragma unroll
    for (int j = 0; j < 4; j++) bias[j] = b1[ncol + j] + b2[ncol + j];

    // park results (bias added) in SMEM tile
    #pragma unroll
    for (int ip = 0; ip < 4; ip++) {
        float lo[4], hi[4];
        #pragma unroll
        for (int j = 0; j < 4; j++) unpack2(acc2[ip][j], lo[j], hi[j]);
        int m0 = ty * 8 + 2 * ip;
        #pragma unroll
        for (int j = 0; j < 4; j++) {
            St[m0][tx * 4 + j]     = lo[j] + bias[j];
            St[m0 + 1][tx * 4 + j] = hi[j] + bias[j];
        }
    }
    __syncthreads();

    // transposed write: gx[t][n][b], dense 512B per warp-instruction
    {
        int lane = tid & 31;
        int wp   = tid >> 5;                 // 0..7
        #pragma unroll
        for (int round = 0; round < 8; round++) {
            int pair = wp * 32 + round * 4 + (lane >> 3);  // 0..255 = (t_l, n_l)
            int t_l  = pair >> 6;
            int n_l  = pair & 63;
            int b0   = (lane & 7) * 4;
            float4 v;
            v.x = St[t_l * 32 + b0 + 0][n_l];
            v.y = St[t_l * 32 + b0 + 1][n_l];
            v.z = St[t_l * 32 + b0 + 2][n_l];
            v.w = St[t_l * 32 + b0 + 3][n_l];
            size_t dst = ((size_t)(brow * 4 + t_l) * G4 + (bcol * 64 + n_l)) * BB + b0;
            *(float4*)&g_gx[dst] = v;
        }
    }
}

// ---------------- backward direction: ONE cell step (unchanged) ----------------
__global__ __launch_bounds__(256) void lstm_bwd_step_kernel(
    const float* __restrict__ x,
    const float* __restrict__ h0,
    const float* __restrict__ c0,
    const float* __restrict__ w_ih,
    const float* __restrict__ w_hh,
    const float* __restrict__ b_ih,
    const float* __restrict__ b_hh,
    float* __restrict__ out)
{
    int tid = threadIdx.x;
    int b = tid & 31;
    int j = blockIdx.x * 8 + (tid >> 5);

    float acc[4] = {0.f, 0.f, 0.f, 0.f};
    const float* xrow = x + ((size_t)b * TT + (TT - 1)) * ID;
    #pragma unroll 4
    for (int k = 0; k < ID; k++) {
        float xv = xrow[k];
        #pragma unroll
        for (int g = 0; g < 4; g++)
            acc[g] += xv * w_ih[(size_t)(g * HD + j) * ID + k];
    }
    const float* hrow = h0 + BB * HD + (size_t)b * HD;
    #pragma unroll 4
    for (int k = 0; k < HD; k++) {
        float hv = hrow[k];
        #pragma unroll
        for (int g = 0; g < 4; g++)
            acc[g] += hv * w_hh[(size_t)(g * HD + j) * HD + k];
    }
    #pragma unroll
    for (int g = 0; g < 4; g++) acc[g] += b_ih[g * HD + j] + b_hh[g * HD + j];

    float ig = 1.f / (1.f + __expf(-acc[0]));
    float fg = 1.f / (1.f + __expf(-acc[1]));
    float gg = tanhf(acc[2]);
    float og = 1.f / (1.f + __expf(-acc[3]));
    float c  = fg * c0[BB * HD + (size_t)b * HD + j] + ig * gg;
    float h  = og * tanhf(c);
    out[b * 1024 + 512 + j] = fmaxf(h, 0.f);
}

// ---------------- forward recurrence ----------------
// 512 threads, 16 warps. warp = k-segment seg (32 k), lane = batch.
// h from global in [k/4][b][4] layout: 8x LDG.128, lane-stride 16B (nL=4, dense).
// w broadcast from SMEM; gx coalesced prefetch; monotonic global barrier.
#define SMEM_FLOATS (16*512 + 16*16*32)
#define SMEM_BYTES  (SMEM_FLOATS * 4)

__device__ __forceinline__ unsigned ld_relaxed_gpu(const unsigned* p) {
    unsigned v;
    asm volatile("ld.relaxed.gpu.u32 %0, [%1];" : "=r"(v) : "l"(p));
    return v;
}
__device__ __forceinline__ void fence_acqrel_gpu() {
    asm volatile("fence.acq_rel.gpu;" ::: "memory");
}
__device__ __forceinline__ void red_add_relaxed_gpu(unsigned* p, unsigned v) {
    asm volatile("red.relaxed.gpu.global.add.u32 [%0], %1;" :: "l"(p), "r"(v));
}

__device__ __forceinline__ float fsig(float x) {
    return __fdividef(1.f, 1.f + __expf(-x));
}
__device__ __forceinline__ float ftanh(float x) {
    return __fdividef(2.f, 1.f + __expf(-2.f * x)) - 1.f;
}

__global__ __launch_bounds__(512) void lstm_fwd_kernel(
    const float* __restrict__ c0,
    const float* __restrict__ w_hh,   // [2048][512]
    float* __restrict__ out)
{
    extern __shared__ float sm[];
    float* w_s  = sm;                        // [16][512]   r = g*4+u
    float* part = sm + 16 * 512;             // [16 seg][16 r][32 b]

    int tid  = threadIdx.x;
    int bx   = blockIdx.x;       // 0..127
    int lane = tid & 31;
    int seg  = tid >> 5;         // k-segment 0..15

    // load w_hh slice: local row r -> global row (r>>2)*512 + bx*4 + (r&3)
    for (int i = tid; i < 16 * 128; i += 512) {
        int r  = i >> 7;
        int kq = i & 127;
        int col = (r >> 2) * HD + bx * 4 + (r & 3);
        *(float4*)&w_s[r * HD + kq * 4] =
            *(const float4*)&w_hh[(size_t)col * HD + kq * 4];
    }

    int u = tid >> 5;            // valid for tid<128 (0..3)
    int b = lane;
    int j = bx * 4 + u;
    float c = 0.f, hv = 0.f;
    if (tid < 128) c = c0[(size_t)b * HD + j];

    const float* wseg = w_s + seg * 32;

    __syncthreads();   // w_s ready; g_hq[0] seeded by init kernel

    for (int step = 0; step < TT; step++) {
        int cur = step & 1;

        // ---- h for this warp's k-window: 8x LDG.128, dense (nL=4) ----
        const float4* hsrc = (const float4*)g_hq[cur] + seg * 8 * 32 + lane;
        float4 h4[8];
        #pragma unroll
        for (int i = 0; i < 8; i++)
            h4[i] = __ldcg(hsrc + i * 32);

        // ---- gx prefetch (coalesced: lane=b contiguous), consumed after sync ----
        float gxv[4];
        if (tid < 128) {
            const float* gp = g_gx + ((size_t)step * G4 + j) * BB + b;
            #pragma unroll
            for (int g = 0; g < 4; g++)
                gxv[g] = __ldcg(gp + (size_t)g * HD * BB);
        }

        // ---- dots: 16 rows x 32 k, w broadcast from SMEM, h in regs ----
        unsigned long long acc[16];
        #pragma unroll
        for (int r = 0; r < 16; r++) acc[r] = 0ull;

        #pragma unroll
        for (int it = 0; it < 8; it++) {
            int k = it * 4;
            unsigned long long ha = pack2(h4[it].x, h4[it].y);
            unsigned long long hb = pack2(h4[it].z, h4[it].w);
            #pragma unroll
            for (int r = 0; r < 16; r++) {
                ulonglong2 w2 = *(const ulonglong2*)(wseg + r * HD + k);
                ffma2(acc[r], w2.x, ha);
                ffma2(acc[r], w2.y, hb);
            }
        }
        #pragma unroll
        for (int r = 0; r < 16; r++) {
            float lo, hi;
            unpack2(acc[r], lo, hi);
            part[(seg * 16 + r) * 32 + lane] = lo + hi;
        }
        __syncthreads();

        // ---- elementwise update: thread (u, b), tid<128 ----
        if (tid < 128) {
            float gate[4];
            #pragma unroll
            for (int g = 0; g < 4; g++) {
                int r = g * 4 + u;
                float s = gxv[g];
                #pragma unroll
                for (int ss = 0; ss < 16; ss++)
                    s += part[(ss * 16 + r) * 32 + b];
                gate[g] = s;
            }
            float ig = fsig(gate[0]);
            float fg = fsig(gate[1]);
            float gg = ftanh(gate[2]);
            float og = fsig(gate[3]);
            c  = fg * c + ig * gg;
            hv = og * ftanh(c);
            // h store: [j>>2][b][j&3]; j>>2 == bx, j&3 == u  -> 4 lines/warp
            g_hq[1 - cur][bx][b][u] = hv;

            asm volatile("bar.sync 1, 128;");   // updaters' h stores done
            if (tid == 0) {
                fence_acqrel_gpu();                       // release h stores
                red_add_relaxed_gpu(&g_bar_count, 1u);    // fire-and-forget
                unsigned target = (unsigned)(step + 1) * 128u;
                if (ld_relaxed_gpu(&g_bar_count) < target) {
                    while (ld_relaxed_gpu(&g_bar_count) < target) { }
                }
                fence_acqrel_gpu();                       // acquire peers' h
            }
        }
        __syncthreads();   // release whole CTA into next step
    }

    if (tid < 128) out[b * 1024 + j] = fmaxf(hv, 0.f);
}

// ---------------- launch ----------------
extern "C" void kernel_launch(void* const* d_in, const int* in_sizes, int n_in,
                              void* d_out, int out_size)
{
    const float* x      = (const float*)d_in[0];
    const float* h0     = (const float*)d_in[1];
    const float* c0     = (const float*)d_in[2];
    const float* w_ih_f = (const float*)d_in[3];
    const float* w_hh_f = (const float*)d_in[4];
    const float* b_ih_f = (const float*)d_in[5];
    const float* b_hh_f = (const float*)d_in[6];
    const float* w_ih_b = (const float*)d_in[7];
    const float* w_hh_b = (const float*)d_in[8];
    const float* b_ih_b = (const float*)d_in[9];
    const float* b_hh_b = (const float*)d_in[10];
    float* out = (float*)d_out;

    cudaFuncSetAttribute(lstm_fwd_kernel,
                         cudaFuncAttributeMaxDynamicSharedMemorySize, SMEM_BYTES);

    init_kernel<<<64, 256>>>(h0);

    dim3 gg(128, 32);
    gx_gemm_kernel<<<gg, 256>>>(x, w_ih_f, b_ih_f, b_hh_f);

    lstm_bwd_step_kernel<<<64, 256>>>(x, h0, c0, w_ih_b, w_hh_b, b_ih_b, b_hh_b, out);

    lstm_fwd_kernel<<<128, 512, SMEM_BYTES>>>(c0, w_hh_f, out);
}